// round 8
// baseline (speedup 1.0000x reference)
#include <cuda_runtime.h>
#include <cstdint>

// ---------------- problem constants ----------------
#define B_    2
#define S_    2048
#define D_    1024
#define H_    16
#define DK_   64
#define BH_   (B_*H_)        // 32
#define M_    (B_*S_)        // 4096
#define NEGV  (-1000000000.0f)
#define LNEPS 1e-6f
#define INVTEMP 0.125f       // 1/sqrt(64)

// ---------------- device scratch (static; no allocations) ----------------
__device__ float g_q[(size_t)BH_*S_*DK_];
__device__ float g_k[(size_t)BH_*S_*DK_];
__device__ float g_v[(size_t)BH_*S_*DK_];
__device__ float g_o[(size_t)M_*D_];
__device__ float g_fc[(size_t)M_*D_];
__device__ float g_rsum[BH_*S_];
__device__ float g_attn[(size_t)BH_*S_*S_];   // fallback if attn not in d_out

// ---------------- tf32 helpers ----------------
__device__ __forceinline__ uint32_t tf32r(float f){
    uint32_t u; asm("cvt.rna.tf32.f32 %0,%1;" : "=r"(u) : "f"(f)); return u;
}

#define MMA_TF32(c,a,b) \
  asm volatile("mma.sync.aligned.m16n8k8.row.col.f32.tf32.tf32.f32 " \
    "{%0,%1,%2,%3},{%4,%5,%6,%7},{%8,%9},{%0,%1,%2,%3};" \
    : "+f"(c[0]),"+f"(c[1]),"+f"(c[2]),"+f"(c[3]) \
    : "r"(a[0]),"r"(a[1]),"r"(a[2]),"r"(a[3]),"r"(b[0]),"r"(b[1]))

// One 32-deep K-chunk of warp-level MMAs.
// As: [m][AP] m-major tf32; Bs: [32][BP] k-major tf32.
// Warp tile: 32 (m) x NB*8 (n).
template<int NB, int AP, int BP>
__device__ __forceinline__ void mma_chunk(const uint32_t* As, const uint32_t* Bs,
        int wm, int wn, int lane, float (*c)[NB][4])
{
    const int r = lane >> 2, q = lane & 3;
    #pragma unroll
    for (int ks = 0; ks < 4; ks++) {
        const int k0 = ks * 8;
        uint32_t a[2][4], b[NB][2];
        #pragma unroll
        for (int im = 0; im < 2; im++) {
            const uint32_t* ap = As + (size_t)(wm + 16*im + r) * AP + k0 + q;
            a[im][0] = ap[0];      a[im][1] = ap[8*AP];
            a[im][2] = ap[4];      a[im][3] = ap[8*AP + 4];
        }
        #pragma unroll
        for (int jn = 0; jn < NB; jn++) {
            const uint32_t* bp = Bs + (size_t)(k0 + q) * BP + wn + 8*jn + r;
            b[jn][0] = bp[0];      b[jn][1] = bp[4*BP];
        }
        #pragma unroll
        for (int im = 0; im < 2; im++)
            #pragma unroll
            for (int jn = 0; jn < NB; jn++)
                MMA_TF32(c[im][jn], a[im], b[jn]);
    }
}

// ---------------- block reduction (blockDim == 256) ----------------
__device__ __forceinline__ float bred_sum(float v, float* red){
    #pragma unroll
    for (int o = 16; o; o >>= 1) v += __shfl_xor_sync(0xffffffffu, v, o);
    if ((threadIdx.x & 31) == 0) red[threadIdx.x >> 5] = v;
    __syncthreads();
    float r = red[0];
    #pragma unroll
    for (int i = 1; i < 8; i++) r += red[i];
    __syncthreads();
    return r;
}

// =======================================================================
// K1: QKV projections (tf32 MMA, 32-deep chunks, 2 CTA/SM).
// Y = X[4096,1024] @ W[1024,1024].  Output layout: [bh][s][dk].
// =======================================================================
__global__ __launch_bounds__(256)
void k_proj(const float* __restrict__ X,
            const float* __restrict__ Wq,
            const float* __restrict__ Wk,
            const float* __restrict__ Wv)
{
    __shared__ uint32_t As[128*36];
    __shared__ uint32_t Bs[32*136];
    const int z = blockIdx.z;
    const float* W = (z == 0) ? Wq : (z == 1) ? Wk : Wv;
    float* DST     = (z == 0) ? g_q : (z == 1) ? g_k : g_v;
    const int n0 = blockIdx.x * 128, m0 = blockIdx.y * 128;
    const int t = threadIdx.x, lane = t & 31, wid = t >> 5;
    const int wm = (wid & 3) * 32, wn = (wid >> 2) * 64;

    float c[2][8][4];
    #pragma unroll
    for (int i=0;i<2;i++)
        #pragma unroll
        for (int j=0;j<8;j++)
            #pragma unroll
            for (int k=0;k<4;k++) c[i][j][k]=0.f;

    for (int k0 = 0; k0 < 1024; k0 += 32) {
        #pragma unroll
        for (int p = 0; p < 4; p++) {               // A: 128x32
            int f = t + p*256, r = f >> 3, c4 = f & 7;
            float4 v = *(const float4*)&X[(size_t)(m0+r)*1024 + k0 + c4*4];
            uint32_t* d = &As[r*36 + c4*4];
            d[0]=tf32r(v.x); d[1]=tf32r(v.y); d[2]=tf32r(v.z); d[3]=tf32r(v.w);
        }
        #pragma unroll
        for (int p = 0; p < 4; p++) {               // B: 32x128
            int f = t + p*256, r = f >> 5, c4 = f & 31;
            float4 v = *(const float4*)&W[(size_t)(k0+r)*1024 + n0 + c4*4];
            uint32_t* d = &Bs[r*136 + c4*4];
            d[0]=tf32r(v.x); d[1]=tf32r(v.y); d[2]=tf32r(v.z); d[3]=tf32r(v.w);
        }
        __syncthreads();
        mma_chunk<8,36,136>(As, Bs, wm, wn, lane, c);
        __syncthreads();
    }
    const int r = lane >> 2, q4 = lane & 3;
    #pragma unroll
    for (int im = 0; im < 2; im++) {
        #pragma unroll
        for (int jn = 0; jn < 8; jn++) {
            const int n = n0 + wn + 8*jn + 2*q4;
            const int hh = n >> 6, nc = n & 63;
            #pragma unroll
            for (int hr = 0; hr < 2; hr++) {
                const int m = m0 + wm + 16*im + r + 8*hr;
                const int b = m >> 11, s = m & 2047;
                *(float2*)&DST[(((size_t)(b*H_ + hh))*S_ + s)*DK_ + nc] =
                    make_float2(c[im][jn][2*hr], c[im][jn][2*hr+1]);
            }
        }
    }
}

// =======================================================================
// K2: k_attn — single-pass attention:
//   loop: QK^T -> e=exp(masked l) (unnormalized) -> write e + PV mma,
//   with register-prefetched K/V tiles; row sums accumulate in registers.
//   epilogue: O = acc/sum AND in-place attn *= 1/sum (k_scale folded in).
// grid (qtile=16, bh=32), 256 threads.
// =======================================================================
__global__ __launch_bounds__(256, 2)
void k_attn(const int* __restrict__ mask, float* __restrict__ attn_ext)
{
    extern __shared__ uint32_t sh[];
    uint32_t* Qs  = sh;                    // [128][68]      8704 w
    uint32_t* Ps  = sh + 8704;             // [128][68]      8704 w
    uint32_t* Bsb = sh + 17408;            // 2 x [32][72]   4608 w
    uint32_t* Vsb = sh + 22016;            // 2 x [32][72]   4608 w
    float* s_red  = (float*)(sh + 26624);  // [2][128]
    float* s_inv  = s_red + 256;           // [128]

    float* attn = attn_ext ? attn_ext : g_attn;
    const int bh = blockIdx.y, b = bh >> 4, h = bh & 15;
    const int m0 = blockIdx.x * 128;
    const float* Q = g_q + (size_t)bh * S_ * DK_;
    const float* K = g_k + (size_t)bh * S_ * DK_;
    const float* V = g_v + (size_t)bh * S_ * DK_;
    const int t = threadIdx.x, lane = t & 31, wid = t >> 5;
    const int wm = (wid & 3) * 32, wc = wid >> 2, wn = wc * 32;
    const int r8 = lane >> 2, q4 = lane & 3;

    // per-thread K/V load coords (fixed across tiles)
    const int lkey = t >> 2;               // 0..63  (key within tile)
    const int lc4  = (t & 3) * 4;          // 0,4,8,12 (dk col group... see below)

    #pragma unroll
    for (int p = 0; p < 8; p++) {          // Q tile 128x64, pitch 68
        int f = t + p*256, rr = f >> 4, c4 = f & 15;
        float4 v = *(const float4*)&Q[(size_t)(m0+rr)*DK_ + c4*4];
        uint32_t* d = &Qs[rr*68 + c4*4];
        d[0]=tf32r(v.x); d[1]=tf32r(v.y); d[2]=tf32r(v.z); d[3]=tf32r(v.w);
    }

    float acc[2][4][4];
    #pragma unroll
    for (int i=0;i<2;i++)
        #pragma unroll
        for (int j=0;j<4;j++)
            #pragma unroll
            for (int k=0;k<4;k++) acc[i][j][k]=0.f;
    float s_acc[4] = {0.f, 0.f, 0.f, 0.f};

    // prefetch tile 0 into registers (pattern: p-th quarter, f = t + p*256)
    float4 kr[4], vr[4];
    #pragma unroll
    for (int p = 0; p < 4; p++) {
        int f = t + p*256, key = f >> 4, c4 = f & 15;
        kr[p] = *(const float4*)&K[(size_t)key*DK_ + c4*4];
        vr[p] = *(const float4*)&V[(size_t)key*DK_ + c4*4];
    }

    for (int kt = 0; kt < 32; kt++) {
        __syncthreads();                   // prev PV mma done (also Qs ready @kt=0)
        #pragma unroll
        for (int p = 0; p < 4; p++) {      // K regs -> smem transposed
            int f = t + p*256, key = f >> 4, c4 = f & 15;
            const int ch = c4 >> 3, colb = (c4 & 7) * 4;
            uint32_t* d = &Bsb[ch*32*72];
            d[(colb+0)*72 + key] = tf32r(kr[p].x);
            d[(colb+1)*72 + key] = tf32r(kr[p].y);
            d[(colb+2)*72 + key] = tf32r(kr[p].z);
            d[(colb+3)*72 + key] = tf32r(kr[p].w);
        }
        #pragma unroll
        for (int p = 0; p < 4; p++) {      // V regs -> smem natural
            int f = t + p*256, rr = f >> 4, c4 = f & 15;
            const int ch = rr >> 5;
            uint32_t* d = &Vsb[ch*32*72 + (rr & 31)*72 + c4*4];
            d[0]=tf32r(vr[p].x); d[1]=tf32r(vr[p].y);
            d[2]=tf32r(vr[p].z); d[3]=tf32r(vr[p].w);
        }
        __syncthreads();

        float c[2][4][4];
        #pragma unroll
        for (int i=0;i<2;i++)
            #pragma unroll
            for (int j=0;j<4;j++)
                #pragma unroll
                for (int k=0;k<4;k++) c[i][j][k]=0.f;
        mma_chunk<4,68,72>(Qs,      Bsb,         wm, wn, lane, c);
        mma_chunk<4,68,72>(Qs + 32, Bsb + 32*72, wm, wn, lane, c);

        // prefetch next K/V tile (latency hidden behind exp + PV mma)
        if (kt < 31) {
            const int n1 = (kt + 1) * 64;
            #pragma unroll
            for (int p = 0; p < 4; p++) {
                int f = t + p*256, key = f >> 4, c4 = f & 15;
                kr[p] = *(const float4*)&K[(size_t)(n1+key)*DK_ + c4*4];
                vr[p] = *(const float4*)&V[(size_t)(n1+key)*DK_ + c4*4];
            }
        }

        // e = mask ? exp(l) : 0 ; write unnormalized e + stage + row sums
        const int n0 = kt * 64;
        #pragma unroll
        for (int im = 0; im < 2; im++)
        #pragma unroll
        for (int hr = 0; hr < 2; hr++) {
            const int rowloc = wm + 16*im + 8*hr + r8;
            const int qg = m0 + rowloc;
            const size_t mrow = (size_t)b*S_*S_ + (size_t)qg*S_;
            const size_t arow = ((size_t)bh*S_ + qg) * S_;
            float s = 0.f;
            #pragma unroll
            for (int jn = 0; jn < 4; jn++) {
                const int colloc = wn + 8*jn + 2*q4;
                const int col = n0 + colloc;
                const int2 mk = *(const int2*)&mask[mrow + col];
                const float ex = mk.x ? __expf(c[im][jn][2*hr]   * INVTEMP) : 0.f;
                const float ey = mk.y ? __expf(c[im][jn][2*hr+1] * INVTEMP) : 0.f;
                s += ex + ey;
                *(float2*)&attn[arow + col] = make_float2(ex, ey);
                Ps[rowloc*68 + colloc]     = tf32r(ex);
                Ps[rowloc*68 + colloc + 1] = tf32r(ey);
            }
            s_acc[im*2 + hr] += s;
        }
        __syncthreads();

        mma_chunk<4,68,72>(Ps,      Vsb,         wm, wn, lane, acc);
        mma_chunk<4,68,72>(Ps + 32, Vsb + 32*72, wm, wn, lane, acc);
    }

    // row-sum reduction: q4 lanes -> warp-column partials -> total
    #pragma unroll
    for (int im = 0; im < 2; im++)
    #pragma unroll
    for (int hr = 0; hr < 2; hr++) {
        const int rowloc = wm + 16*im + 8*hr + r8;
        float s = s_acc[im*2 + hr];
        s += __shfl_xor_sync(0xffffffffu, s, 1);
        s += __shfl_xor_sync(0xffffffffu, s, 2);
        if (q4 == 0) s_red[wc*128 + rowloc] = s;
    }
    __syncthreads();
    if (t < 128) {
        const float tot = s_red[t] + s_red[128 + t];
        g_rsum[bh*S_ + m0 + t] = tot;
        s_inv[t] = 1.f / tot;
    }
    __syncthreads();

    // epilogue 1: O = acc * inv, merged [b*S+q][h*64+n]
    #pragma unroll
    for (int im = 0; im < 2; im++)
    #pragma unroll
    for (int hr = 0; hr < 2; hr++) {
        const int rowloc = wm + 16*im + 8*hr + r8;
        const int qg = m0 + rowloc;
        const float inv = s_inv[rowloc];
        float* orow = &g_o[(size_t)(b*S_ + qg)*D_ + h*DK_];
        #pragma unroll
        for (int jn = 0; jn < 4; jn++) {
            const int n = wn + 8*jn + 2*q4;
            *(float2*)&orow[n] = make_float2(acc[im][jn][2*hr] * inv,
                                             acc[im][jn][2*hr+1] * inv);
        }
    }

    // epilogue 2 (k_scale folded in): attn rows *= inv, in place.
    // This CTA exclusively owns rows [m0, m0+128) of head bh.
    for (int rr = wid; rr < 128; rr += 8) {
        const float inv = s_inv[rr];
        float4* p = (float4*)(attn + ((size_t)bh*S_ + m0 + rr) * S_);
        #pragma unroll
        for (int u = 0; u < 16; u++) {
            float4 v = p[lane + 32*u];
            v.x *= inv; v.y *= inv; v.z *= inv; v.w *= inv;
            p[lane + 32*u] = v;
        }
    }
}

// =======================================================================
// K3: fc = O[4096,1024] @ w_fc[1024,1024] + residual (tf32)
// =======================================================================
__global__ __launch_bounds__(256)
void k_fc(const float* __restrict__ X, const float* __restrict__ W)
{
    __shared__ uint32_t As[128*36];
    __shared__ uint32_t Bs[32*136];
    const int n0 = blockIdx.x * 128, m0 = blockIdx.y * 128;
    const int t = threadIdx.x, lane = t & 31, wid = t >> 5;
    const int wm = (wid & 3) * 32, wn = (wid >> 2) * 64;

    float c[2][8][4];
    #pragma unroll
    for (int i=0;i<2;i++)
        #pragma unroll
        for (int j=0;j<8;j++)
            #pragma unroll
            for (int k=0;k<4;k++) c[i][j][k]=0.f;

    for (int k0 = 0; k0 < 1024; k0 += 32) {
        #pragma unroll
        for (int p = 0; p < 4; p++) {
            int f = t + p*256, r = f >> 3, c4 = f & 7;
            float4 v = *(const float4*)&g_o[(size_t)(m0+r)*1024 + k0 + c4*4];
            uint32_t* d = &As[r*36 + c4*4];
            d[0]=tf32r(v.x); d[1]=tf32r(v.y); d[2]=tf32r(v.z); d[3]=tf32r(v.w);
        }
        #pragma unroll
        for (int p = 0; p < 4; p++) {
            int f = t + p*256, r = f >> 5, c4 = f & 31;
            float4 v = *(const float4*)&W[(size_t)(k0+r)*1024 + n0 + c4*4];
            uint32_t* d = &Bs[r*136 + c4*4];
            d[0]=tf32r(v.x); d[1]=tf32r(v.y); d[2]=tf32r(v.z); d[3]=tf32r(v.w);
        }
        __syncthreads();
        mma_chunk<8,36,136>(As, Bs, wm, wn, lane, c);
        __syncthreads();
    }
    const int r = lane >> 2, q4 = lane & 3;
    #pragma unroll
    for (int im = 0; im < 2; im++) {
        #pragma unroll
        for (int hr = 0; hr < 2; hr++) {
            const int m = m0 + wm + 16*im + r + 8*hr;
            #pragma unroll
            for (int jn = 0; jn < 8; jn++) {
                const int n = n0 + wn + 8*jn + 2*q4;
                const float2 res = *(const float2*)&X[(size_t)m*D_ + n];
                *(float2*)&g_fc[(size_t)m*D_ + n] =
                    make_float2(c[im][jn][2*hr] + res.x, c[im][jn][2*hr+1] + res.y);
            }
        }
    }
}

// =======================================================================
// K4: LayerNorm over last dim (1024), write final out region.
// =======================================================================
__global__ __launch_bounds__(256)
void k_ln(const float* __restrict__ gamma, const float* __restrict__ beta,
          float* __restrict__ out)
{
    __shared__ float red[8];
    const int m = blockIdx.x, t = threadIdx.x;
    const float* x = g_fc + (size_t)m * D_;
    float v[4];
    #pragma unroll
    for (int u = 0; u < 4; u++) v[u] = x[t + 256 * u];
    float s = v[0] + v[1] + v[2] + v[3];
    const float mu = bred_sum(s, red) * (1.0f / D_);
    float d2 = 0.f;
    #pragma unroll
    for (int u = 0; u < 4; u++) { float d = v[u] - mu; d2 += d * d; }
    const float var = bred_sum(d2, red) * (1.0f / D_);
    const float rstd = rsqrtf(var + LNEPS);
    #pragma unroll
    for (int u = 0; u < 4; u++) {
        const int c = t + 256 * u;
        out[(size_t)m * D_ + c] = (v[u] - mu) * rstd * gamma[c] + beta[c];
    }
}

// =======================================================================
extern "C" void kernel_launch(void* const* d_in, const int* in_sizes, int n_in,
                              void* d_out, int out_size)
{
    (void)in_sizes; (void)n_in;
    const float* qkv  = (const float*)d_in[0];
    const int*   mask = (const int*)  d_in[1];
    const float* w_qs = (const float*)d_in[2];
    const float* w_ks = (const float*)d_in[3];
    const float* w_vs = (const float*)d_in[4];
    const float* w_fc = (const float*)d_in[5];
    const float* ga   = (const float*)d_in[6];
    const float* be   = (const float*)d_in[7];
    float* out = (float*)d_out;

    const int OUT_ELEMS  = M_ * D_;                        // 4194304
    const long long ATTN_ELEMS = (long long)BH_ * S_ * S_; // 134217728
    float* attn_ext = ((long long)out_size >= OUT_ELEMS + ATTN_ELEMS)
                        ? out + OUT_ELEMS : nullptr;

    const int SMEM_ATTN = (8704 + 8704 + 4608 + 4608 + 256 + 128) * 4; // 108032 B
    cudaFuncSetAttribute(k_attn, cudaFuncAttributeMaxDynamicSharedMemorySize, SMEM_ATTN);

    k_proj <<<dim3(8, 32, 3), 256>>>(qkv, w_qs, w_ks, w_vs);
    k_attn <<<dim3(16, 32), 256, SMEM_ATTN>>>(mask, attn_ext);
    k_fc   <<<dim3(8, 32), 256>>>(qkv, w_fc);
    k_ln   <<<M_, 256>>>(ga, be, out);
}

// round 9
// speedup vs baseline: 1.0243x; 1.0243x over previous
#include <cuda_runtime.h>
#include <cstdint>

// ---------------- problem constants ----------------
#define B_    2
#define S_    2048
#define D_    1024
#define H_    16
#define DK_   64
#define BH_   (B_*H_)        // 32
#define M_    (B_*S_)        // 4096
#define NEGV  (-1000000000.0f)
#define LNEPS 1e-6f
#define INVTEMP 0.125f       // 1/sqrt(64)

// ---------------- device scratch (static; no allocations) ----------------
__device__ float g_q[(size_t)BH_*S_*DK_];
__device__ float g_k[(size_t)BH_*S_*DK_];
__device__ float g_v[(size_t)BH_*S_*DK_];
__device__ float g_o[(size_t)M_*D_];
__device__ float g_fc[(size_t)M_*D_];
__device__ float g_rsum[BH_*S_];
__device__ float g_attn[(size_t)BH_*S_*S_];   // fallback if attn not in d_out

// ---------------- tf32 helpers ----------------
__device__ __forceinline__ uint32_t tf32r(float f){
    uint32_t u; asm("cvt.rna.tf32.f32 %0,%1;" : "=r"(u) : "f"(f)); return u;
}

#define MMA_TF32(c,a,b) \
  asm volatile("mma.sync.aligned.m16n8k8.row.col.f32.tf32.tf32.f32 " \
    "{%0,%1,%2,%3},{%4,%5,%6,%7},{%8,%9},{%0,%1,%2,%3};" \
    : "+f"(c[0]),"+f"(c[1]),"+f"(c[2]),"+f"(c[3]) \
    : "r"(a[0]),"r"(a[1]),"r"(a[2]),"r"(a[3]),"r"(b[0]),"r"(b[1]))

// One 32-deep K-chunk of warp-level MMAs.
// As: [m][AP] m-major tf32; Bs: [32][BP] k-major tf32.
// Warp tile: 32 (m) x NB*8 (n).
template<int NB, int AP, int BP>
__device__ __forceinline__ void mma_chunk(const uint32_t* As, const uint32_t* Bs,
        int wm, int wn, int lane, float (*c)[NB][4])
{
    const int r = lane >> 2, q = lane & 3;
    #pragma unroll
    for (int ks = 0; ks < 4; ks++) {
        const int k0 = ks * 8;
        uint32_t a[2][4], b[NB][2];
        #pragma unroll
        for (int im = 0; im < 2; im++) {
            const uint32_t* ap = As + (size_t)(wm + 16*im + r) * AP + k0 + q;
            a[im][0] = ap[0];      a[im][1] = ap[8*AP];
            a[im][2] = ap[4];      a[im][3] = ap[8*AP + 4];
        }
        #pragma unroll
        for (int jn = 0; jn < NB; jn++) {
            const uint32_t* bp = Bs + (size_t)(k0 + q) * BP + wn + 8*jn + r;
            b[jn][0] = bp[0];      b[jn][1] = bp[4*BP];
        }
        #pragma unroll
        for (int im = 0; im < 2; im++)
            #pragma unroll
            for (int jn = 0; jn < NB; jn++)
                MMA_TF32(c[im][jn], a[im], b[jn]);
    }
}

// ---------------- block reduction (blockDim == 256) ----------------
__device__ __forceinline__ float bred_sum(float v, float* red){
    #pragma unroll
    for (int o = 16; o; o >>= 1) v += __shfl_xor_sync(0xffffffffu, v, o);
    if ((threadIdx.x & 31) == 0) red[threadIdx.x >> 5] = v;
    __syncthreads();
    float r = red[0];
    #pragma unroll
    for (int i = 1; i < 8; i++) r += red[i];
    __syncthreads();
    return r;
}

// =======================================================================
// K1: QKV projections (tf32 MMA, 32-deep chunks, 2 CTA/SM).
// Y = X[4096,1024] @ W[1024,1024].  Output layout: [bh][s][dk].
// =======================================================================
__global__ __launch_bounds__(256)
void k_proj(const float* __restrict__ X,
            const float* __restrict__ Wq,
            const float* __restrict__ Wk,
            const float* __restrict__ Wv)
{
    __shared__ uint32_t As[128*36];
    __shared__ uint32_t Bs[32*136];
    const int z = blockIdx.z;
    const float* W = (z == 0) ? Wq : (z == 1) ? Wk : Wv;
    float* DST     = (z == 0) ? g_q : (z == 1) ? g_k : g_v;
    const int n0 = blockIdx.x * 128, m0 = blockIdx.y * 128;
    const int t = threadIdx.x, lane = t & 31, wid = t >> 5;
    const int wm = (wid & 3) * 32, wn = (wid >> 2) * 64;

    float c[2][8][4];
    #pragma unroll
    for (int i=0;i<2;i++)
        #pragma unroll
        for (int j=0;j<8;j++)
            #pragma unroll
            for (int k=0;k<4;k++) c[i][j][k]=0.f;

    for (int k0 = 0; k0 < 1024; k0 += 32) {
        #pragma unroll
        for (int p = 0; p < 4; p++) {               // A: 128x32
            int f = t + p*256, r = f >> 3, c4 = f & 7;
            float4 v = *(const float4*)&X[(size_t)(m0+r)*1024 + k0 + c4*4];
            uint32_t* d = &As[r*36 + c4*4];
            d[0]=tf32r(v.x); d[1]=tf32r(v.y); d[2]=tf32r(v.z); d[3]=tf32r(v.w);
        }
        #pragma unroll
        for (int p = 0; p < 4; p++) {               // B: 32x128
            int f = t + p*256, r = f >> 5, c4 = f & 31;
            float4 v = *(const float4*)&W[(size_t)(k0+r)*1024 + n0 + c4*4];
            uint32_t* d = &Bs[r*136 + c4*4];
            d[0]=tf32r(v.x); d[1]=tf32r(v.y); d[2]=tf32r(v.z); d[3]=tf32r(v.w);
        }
        __syncthreads();
        mma_chunk<8,36,136>(As, Bs, wm, wn, lane, c);
        __syncthreads();
    }
    const int r = lane >> 2, q4 = lane & 3;
    #pragma unroll
    for (int im = 0; im < 2; im++) {
        #pragma unroll
        for (int jn = 0; jn < 8; jn++) {
            const int n = n0 + wn + 8*jn + 2*q4;
            const int hh = n >> 6, nc = n & 63;
            #pragma unroll
            for (int hr = 0; hr < 2; hr++) {
                const int m = m0 + wm + 16*im + r + 8*hr;
                const int b = m >> 11, s = m & 2047;
                *(float2*)&DST[(((size_t)(b*H_ + hh))*S_ + s)*DK_ + nc] =
                    make_float2(c[im][jn][2*hr], c[im][jn][2*hr+1]);
            }
        }
    }
}

// =======================================================================
// K2: k_attn — single-pass attention:
//   loop: QK^T -> e=exp(masked l) (unnormalized) -> write e + PV mma;
//   row sums accumulate in registers.
//   epilogue: O = acc/sum AND in-place attn *= 1/sum (scale folded in).
// grid (qtile=16, bh=32), 256 threads.  NO register prefetch (R8 lesson).
// =======================================================================
__global__ __launch_bounds__(256, 2)
void k_attn(const int* __restrict__ mask, float* __restrict__ attn_ext)
{
    extern __shared__ uint32_t sh[];
    uint32_t* Qs  = sh;                    // [128][68]      8704 w
    uint32_t* Ps  = sh + 8704;             // [128][68]      8704 w
    uint32_t* Bsb = sh + 17408;            // 2 x [32][72]   4608 w
    uint32_t* Vsb = sh + 22016;            // 2 x [32][72]   4608 w
    float* s_red  = (float*)(sh + 26624);  // [2][128]
    float* s_inv  = s_red + 256;           // [128]

    float* attn = attn_ext ? attn_ext : g_attn;
    const int bh = blockIdx.y, b = bh >> 4, h = bh & 15;
    const int m0 = blockIdx.x * 128;
    const float* Q = g_q + (size_t)bh * S_ * DK_;
    const float* K = g_k + (size_t)bh * S_ * DK_;
    const float* V = g_v + (size_t)bh * S_ * DK_;
    const int t = threadIdx.x, lane = t & 31, wid = t >> 5;
    const int wm = (wid & 3) * 32, wc = wid >> 2, wn = wc * 32;
    const int r8 = lane >> 2, q4 = lane & 3;

    #pragma unroll
    for (int p = 0; p < 8; p++) {          // Q tile 128x64, pitch 68
        int f = t + p*256, rr = f >> 4, c4 = f & 15;
        float4 v = *(const float4*)&Q[(size_t)(m0+rr)*DK_ + c4*4];
        uint32_t* d = &Qs[rr*68 + c4*4];
        d[0]=tf32r(v.x); d[1]=tf32r(v.y); d[2]=tf32r(v.z); d[3]=tf32r(v.w);
    }

    float acc[2][4][4];
    #pragma unroll
    for (int i=0;i<2;i++)
        #pragma unroll
        for (int j=0;j<4;j++)
            #pragma unroll
            for (int k=0;k<4;k++) acc[i][j][k]=0.f;
    float s_acc[4] = {0.f, 0.f, 0.f, 0.f};

    for (int kt = 0; kt < 32; kt++) {
        const int n0 = kt * 64;
        __syncthreads();                   // prev PV mma done (also Qs ready @kt=0)
        #pragma unroll
        for (int p = 0; p < 4; p++) {      // K 64keys x 64dk transposed
            int f = t + p*256, key = f >> 4, c4 = f & 15;
            const int ch = c4 >> 3, colb = (c4 & 7) * 4;
            float4 v = *(const float4*)&K[(size_t)(n0+key)*DK_ + c4*4];
            uint32_t* d = &Bsb[ch*32*72];
            d[(colb+0)*72 + key] = tf32r(v.x);
            d[(colb+1)*72 + key] = tf32r(v.y);
            d[(colb+2)*72 + key] = tf32r(v.z);
            d[(colb+3)*72 + key] = tf32r(v.w);
        }
        #pragma unroll
        for (int p = 0; p < 4; p++) {      // V 64keys x 64 natural
            int f = t + p*256, rr = f >> 4, c4 = f & 15;
            const int ch = rr >> 5;
            float4 v = *(const float4*)&V[(size_t)(n0+rr)*DK_ + c4*4];
            uint32_t* d = &Vsb[ch*32*72 + (rr & 31)*72 + c4*4];
            d[0]=tf32r(v.x); d[1]=tf32r(v.y); d[2]=tf32r(v.z); d[3]=tf32r(v.w);
        }
        __syncthreads();

        float c[2][4][4];
        #pragma unroll
        for (int i=0;i<2;i++)
            #pragma unroll
            for (int j=0;j<4;j++)
                #pragma unroll
                for (int k=0;k<4;k++) c[i][j][k]=0.f;
        mma_chunk<4,68,72>(Qs,      Bsb,         wm, wn, lane, c);
        mma_chunk<4,68,72>(Qs + 32, Bsb + 32*72, wm, wn, lane, c);

        // e = mask ? exp(l) : 0 ; write unnormalized e + stage + row sums
        #pragma unroll
        for (int im = 0; im < 2; im++)
        #pragma unroll
        for (int hr = 0; hr < 2; hr++) {
            const int rowloc = wm + 16*im + 8*hr + r8;
            const int qg = m0 + rowloc;
            const size_t mrow = (size_t)b*S_*S_ + (size_t)qg*S_;
            const size_t arow = ((size_t)bh*S_ + qg) * S_;
            float s = 0.f;
            #pragma unroll
            for (int jn = 0; jn < 4; jn++) {
                const int colloc = wn + 8*jn + 2*q4;
                const int col = n0 + colloc;
                const int2 mk = *(const int2*)&mask[mrow + col];
                const float ex = mk.x ? __expf(c[im][jn][2*hr]   * INVTEMP) : 0.f;
                const float ey = mk.y ? __expf(c[im][jn][2*hr+1] * INVTEMP) : 0.f;
                s += ex + ey;
                *(float2*)&attn[arow + col] = make_float2(ex, ey);
                Ps[rowloc*68 + colloc]     = tf32r(ex);
                Ps[rowloc*68 + colloc + 1] = tf32r(ey);
            }
            s_acc[im*2 + hr] += s;
        }
        __syncthreads();

        mma_chunk<4,68,72>(Ps,      Vsb,         wm, wn, lane, acc);
        mma_chunk<4,68,72>(Ps + 32, Vsb + 32*72, wm, wn, lane, acc);
    }

    // row-sum reduction: q4 lanes -> warp-column partials -> total
    #pragma unroll
    for (int im = 0; im < 2; im++)
    #pragma unroll
    for (int hr = 0; hr < 2; hr++) {
        const int rowloc = wm + 16*im + 8*hr + r8;
        float s = s_acc[im*2 + hr];
        s += __shfl_xor_sync(0xffffffffu, s, 1);
        s += __shfl_xor_sync(0xffffffffu, s, 2);
        if (q4 == 0) s_red[wc*128 + rowloc] = s;
    }
    __syncthreads();
    if (t < 128) {
        const float tot = s_red[t] + s_red[128 + t];
        g_rsum[bh*S_ + m0 + t] = tot;
        s_inv[t] = 1.f / tot;
    }
    __syncthreads();

    // epilogue 1: O = acc * inv, merged [b*S+q][h*64+n]
    #pragma unroll
    for (int im = 0; im < 2; im++)
    #pragma unroll
    for (int hr = 0; hr < 2; hr++) {
        const int rowloc = wm + 16*im + 8*hr + r8;
        const int qg = m0 + rowloc;
        const float inv = s_inv[rowloc];
        float* orow = &g_o[(size_t)(b*S_ + qg)*D_ + h*DK_];
        #pragma unroll
        for (int jn = 0; jn < 4; jn++) {
            const int n = wn + 8*jn + 2*q4;
            *(float2*)&orow[n] = make_float2(acc[im][jn][2*hr] * inv,
                                             acc[im][jn][2*hr+1] * inv);
        }
    }

    // epilogue 2 (scale folded in): attn rows *= inv, in place.
    // This CTA exclusively owns rows [m0, m0+128) of head bh.
    for (int rr = wid; rr < 128; rr += 8) {
        const float inv = s_inv[rr];
        float4* p = (float4*)(attn + ((size_t)bh*S_ + m0 + rr) * S_);
        #pragma unroll
        for (int u = 0; u < 16; u++) {
            float4 v = p[lane + 32*u];
            v.x *= inv; v.y *= inv; v.z *= inv; v.w *= inv;
            p[lane + 32*u] = v;
        }
    }
}

// =======================================================================
// K3: fc = O[4096,1024] @ w_fc[1024,1024] + residual (tf32)
// =======================================================================
__global__ __launch_bounds__(256)
void k_fc(const float* __restrict__ X, const float* __restrict__ W)
{
    __shared__ uint32_t As[128*36];
    __shared__ uint32_t Bs[32*136];
    const int n0 = blockIdx.x * 128, m0 = blockIdx.y * 128;
    const int t = threadIdx.x, lane = t & 31, wid = t >> 5;
    const int wm = (wid & 3) * 32, wn = (wid >> 2) * 64;

    float c[2][8][4];
    #pragma unroll
    for (int i=0;i<2;i++)
        #pragma unroll
        for (int j=0;j<8;j++)
            #pragma unroll
            for (int k=0;k<4;k++) c[i][j][k]=0.f;

    for (int k0 = 0; k0 < 1024; k0 += 32) {
        #pragma unroll
        for (int p = 0; p < 4; p++) {
            int f = t + p*256, r = f >> 3, c4 = f & 7;
            float4 v = *(const float4*)&g_o[(size_t)(m0+r)*1024 + k0 + c4*4];
            uint32_t* d = &As[r*36 + c4*4];
            d[0]=tf32r(v.x); d[1]=tf32r(v.y); d[2]=tf32r(v.z); d[3]=tf32r(v.w);
        }
        #pragma unroll
        for (int p = 0; p < 4; p++) {
            int f = t + p*256, r = f >> 5, c4 = f & 31;
            float4 v = *(const float4*)&W[(size_t)(k0+r)*1024 + n0 + c4*4];
            uint32_t* d = &Bs[r*136 + c4*4];
            d[0]=tf32r(v.x); d[1]=tf32r(v.y); d[2]=tf32r(v.z); d[3]=tf32r(v.w);
        }
        __syncthreads();
        mma_chunk<8,36,136>(As, Bs, wm, wn, lane, c);
        __syncthreads();
    }
    const int r = lane >> 2, q4 = lane & 3;
    #pragma unroll
    for (int im = 0; im < 2; im++) {
        #pragma unroll
        for (int hr = 0; hr < 2; hr++) {
            const int m = m0 + wm + 16*im + r + 8*hr;
            #pragma unroll
            for (int jn = 0; jn < 8; jn++) {
                const int n = n0 + wn + 8*jn + 2*q4;
                const float2 res = *(const float2*)&X[(size_t)m*D_ + n];
                *(float2*)&g_fc[(size_t)m*D_ + n] =
                    make_float2(c[im][jn][2*hr] + res.x, c[im][jn][2*hr+1] + res.y);
            }
        }
    }
}

// =======================================================================
// K4: LayerNorm over last dim (1024), write final out region.
// =======================================================================
__global__ __launch_bounds__(256)
void k_ln(const float* __restrict__ gamma, const float* __restrict__ beta,
          float* __restrict__ out)
{
    __shared__ float red[8];
    const int m = blockIdx.x, t = threadIdx.x;
    const float* x = g_fc + (size_t)m * D_;
    float v[4];
    #pragma unroll
    for (int u = 0; u < 4; u++) v[u] = x[t + 256 * u];
    float s = v[0] + v[1] + v[2] + v[3];
    const float mu = bred_sum(s, red) * (1.0f / D_);
    float d2 = 0.f;
    #pragma unroll
    for (int u = 0; u < 4; u++) { float d = v[u] - mu; d2 += d * d; }
    const float var = bred_sum(d2, red) * (1.0f / D_);
    const float rstd = rsqrtf(var + LNEPS);
    #pragma unroll
    for (int u = 0; u < 4; u++) {
        const int c = t + 256 * u;
        out[(size_t)m * D_ + c] = (v[u] - mu) * rstd * gamma[c] + beta[c];
    }
}

// =======================================================================
extern "C" void kernel_launch(void* const* d_in, const int* in_sizes, int n_in,
                              void* d_out, int out_size)
{
    (void)in_sizes; (void)n_in;
    const float* qkv  = (const float*)d_in[0];
    const int*   mask = (const int*)  d_in[1];
    const float* w_qs = (const float*)d_in[2];
    const float* w_ks = (const float*)d_in[3];
    const float* w_vs = (const float*)d_in[4];
    const float* w_fc = (const float*)d_in[5];
    const float* ga   = (const float*)d_in[6];
    const float* be   = (const float*)d_in[7];
    float* out = (float*)d_out;

    const int OUT_ELEMS  = M_ * D_;                        // 4194304
    const long long ATTN_ELEMS = (long long)BH_ * S_ * S_; // 134217728
    float* attn_ext = ((long long)out_size >= OUT_ELEMS + ATTN_ELEMS)
                        ? out + OUT_ELEMS : nullptr;

    const int SMEM_ATTN = (8704 + 8704 + 4608 + 4608 + 256 + 128) * 4; // 108032 B
    cudaFuncSetAttribute(k_attn, cudaFuncAttributeMaxDynamicSharedMemorySize, SMEM_ATTN);

    k_proj <<<dim3(8, 32, 3), 256>>>(qkv, w_qs, w_ks, w_vs);
    k_attn <<<dim3(16, 32), 256, SMEM_ATTN>>>(mask, attn_ext);
    k_fc   <<<dim3(8, 32), 256>>>(qkv, w_fc);
    k_ln   <<<M_, 256>>>(ga, be, out);
}